// round 13
// baseline (speedup 1.0000x reference)
#include <cuda_runtime.h>
#include <cuda_fp16.h>
#include <math.h>

// ---------------------------------------------------------------------------
// Pyramid scratch.
// tex0: float4 levels 1..7 (all kept — tiny).
// tex1: float4 levels 3..9 only (L1/L2 never materialized; cold fallback
//       recomputes exactly from the base texture, P ~ 3e-9).
// g_hotP: PAIRED packed half4 hot set (uint4 per texel = (t[x], t[x+1clamp])):
//         tex1 L4-9 at [0,8190), tex0 L3-7 at [8192,10238)  (uint4 units).
// Hot texels stored CENTERED: tex1 +1.0, tex0 +2.0.
// ---------------------------------------------------------------------------
__device__ float4 g_p0[32766];
__device__ float4 g_p1[32766];     // tex1 L3..L9, L3 at offset 0
__device__ uint4  g_hotP[10240];   // paired half4 texels, 160KB
__device__ unsigned g_cnt[12];     // per-face completion counters (self-reset)

__constant__ int OFF0[8]   = {0, 0, 24576, 30720, 32256, 32640, 32736, 32760};
__constant__ int OFF1G[10] = {0, 0, 0, 0, 24576, 30720, 32256, 32640,
                              32736, 32760};                  // tex1, L3=0
// hot texel offsets (uint4 units)
__constant__ int SM1OFF[10] = {0, 0, 0, 0, 0, 6144, 7680, 8064, 8160, 8184};
__constant__ int SM0OFF[8]  = {0, 0, 0, 8192, 9728, 10112, 10208, 10232};

__device__ __forceinline__ uint2 pack3(float x, float y, float z) {
    __half2 a = __floats2half2_rn(x, y);
    __half2 b = __floats2half2_rn(z, 0.0f);
    uint2 r;
    r.x = *reinterpret_cast<unsigned*>(&a);
    r.y = *reinterpret_cast<unsigned*>(&b);
    return r;
}

__device__ __forceinline__ float3 unpack3w(unsigned lo, unsigned hi) {
    float2 xy = __half22float2(*reinterpret_cast<__half2*>(&lo));
    float2 zw = __half22float2(*reinterpret_cast<__half2*>(&hi));
    return make_float3(xy.x, xy.y, zw.x);
}

// pairs for one level, reading the level via L2 (__ldcg)
__device__ void write_pairs_g(const float4* __restrict__ src,
                              uint4* __restrict__ dst,
                              int R, float center, int tid) {
    for (int i = tid; i < R * R; i += 256) {
        int x = i % R;
        float4 v0 = __ldcg(src + i);
        float4 v1 = __ldcg(src + ((x < R - 1) ? i + 1 : i));
        uint2 p0 = pack3(v0.x + center, v0.y + center, v0.z + center);
        uint2 p1 = pack3(v1.x + center, v1.y + center, v1.z + center);
        dst[i] = make_uint4(p0.x, p0.y, p1.x, p1.y);
    }
}

// tail reduction for one face (runs inside buildA's last block per face)
__device__ void face_tail(int is_t1, int f, int tid) {
    float4* pyr; const int* goff; const int* soff;
    int baseR, lmax; float center;
    if (is_t1) { pyr = g_p1; goff = OFF1G; soff = SM1OFF;
                 baseR = 512; lmax = 9; center = 1.0f; }
    else       { pyr = g_p0; goff = OFF0;  soff = SM0OFF;
                 baseR = 128; lmax = 7; center = 2.0f; }

    if (!is_t1) {   // tex0 L3 belongs to the hot set
        int R3 = 16;
        write_pairs_g(pyr + goff[3] + (size_t)f * R3 * R3,
                      g_hotP + soff[3] + f * R3 * R3, R3, center, tid);
    }
    for (int l = 4; l <= lmax; l++) {
        int R  = baseR >> l;
        int Rp = R << 1;
        const float4* prev = pyr + goff[l - 1] + (size_t)f * Rp * Rp;
        float4* dst = pyr + goff[l] + (size_t)f * R * R;
        for (int i = tid; i < R * R; i += 256) {
            int x = i % R, y = i / R;
            const float4* p = prev + (size_t)(2 * y) * Rp + 2 * x;
            const float4* q = p + Rp;
            float4 a0 = __ldcg(p), a1 = __ldcg(p + 1);
            float4 b0 = __ldcg(q), b1 = __ldcg(q + 1);
            dst[i] = make_float4(0.25f * (a0.x + a1.x + b0.x + b1.x),
                                 0.25f * (a0.y + a1.y + b0.y + b1.y),
                                 0.25f * (a0.z + a1.z + b0.z + b1.z), 0.0f);
        }
        __threadfence();
        __syncthreads();
        write_pairs_g(dst, g_hotP + soff[l] + f * R * R, R, center, tid);
        __threadfence();
        __syncthreads();
    }
}

// ---------------------------------------------------------------------------
// buildA: L1..L3 of both pyramids (R10 direct-load form) + fused tails.
// 256 threads, 32x16 L1 tiles. tex1 L1/L2 smem-only; only L3 stored.
// ---------------------------------------------------------------------------
__device__ __forceinline__ void build_tile(
    const float* __restrict__ in, int inRowF,
    float4* __restrict__ L1g,      // may be null (tex1)
    float4* __restrict__ L2g,      // may be null (tex1)
    float4* __restrict__ L3g, int R1,
    int bx, int by, int tid,
    float4* s1, float4* s2)
{
    int lx2 = (tid & 15) * 2;
    int ly  = tid >> 4;
    int X0 = bx * 32 + lx2;
    int Y  = by * 16 + ly;

    const float* r0 = in + (size_t)(2 * Y) * inRowF + 6 * X0;
    const float* r1 = r0 + inRowF;
    float a[12], b[12];
    #pragma unroll
    for (int q = 0; q < 3; q++) {
        *(float4*)(a + 4 * q) = __ldg((const float4*)r0 + q);
        *(float4*)(b + 4 * q) = __ldg((const float4*)r1 + q);
    }
    #pragma unroll
    for (int k = 0; k < 2; k++) {
        float cx = 0.25f * (a[6*k+0] + a[6*k+3] + b[6*k+0] + b[6*k+3]);
        float cy = 0.25f * (a[6*k+1] + a[6*k+4] + b[6*k+1] + b[6*k+4]);
        float cz = 0.25f * (a[6*k+2] + a[6*k+5] + b[6*k+2] + b[6*k+5]);
        float4 t = make_float4(cx, cy, cz, 0.0f);
        s1[ly * 32 + lx2 + k] = t;
        if (L1g) L1g[(size_t)Y * R1 + X0 + k] = t;
    }
    __syncthreads();

    if (tid < 128) {
        int x2 = tid & 15, y2 = tid >> 4;
        float4 p00 = s1[(2*y2) * 32 + 2*x2];
        float4 p01 = s1[(2*y2) * 32 + 2*x2 + 1];
        float4 p10 = s1[(2*y2+1) * 32 + 2*x2];
        float4 p11 = s1[(2*y2+1) * 32 + 2*x2 + 1];
        float4 m = make_float4(0.25f * (p00.x + p01.x + p10.x + p11.x),
                               0.25f * (p00.y + p01.y + p10.y + p11.y),
                               0.25f * (p00.z + p01.z + p10.z + p11.z), 0.0f);
        s2[y2 * 16 + x2] = m;
        if (L2g) {
            int R2 = R1 >> 1;
            L2g[(size_t)(by * 8 + y2) * R2 + bx * 16 + x2] = m;
        }
    }
    __syncthreads();

    if (tid < 32) {
        int x3 = tid & 7, y3 = tid >> 3;
        float4 p00 = s2[(2*y3) * 16 + 2*x3];
        float4 p01 = s2[(2*y3) * 16 + 2*x3 + 1];
        float4 p10 = s2[(2*y3+1) * 16 + 2*x3];
        float4 p11 = s2[(2*y3+1) * 16 + 2*x3 + 1];
        float4 m = make_float4(0.25f * (p00.x + p01.x + p10.x + p11.x),
                               0.25f * (p00.y + p01.y + p10.y + p11.y),
                               0.25f * (p00.z + p01.z + p10.z + p11.z), 0.0f);
        int R3 = R1 >> 2;
        L3g[(size_t)(by * 4 + y3) * R3 + bx * 8 + x3] = m;
    }
}

__global__ void __launch_bounds__(256) buildA(const float* __restrict__ t0,
                                              const float* __restrict__ t1) {
    __shared__ float4 s1[32 * 16];
    __shared__ float4 s2[16 * 8];
    __shared__ int s_exec;
    int b = blockIdx.x, tid = threadIdx.x;
    int is_t1, f;
    if (b < 768) {                       // tex1: 6 faces x 128 tiles
        is_t1 = 1; f = b >> 7;
        int q = b & 127;
        int bx = q & 7, by = q >> 3;
        build_tile(t1 + (size_t)f * 512 * 512 * 3, 1536,
                   nullptr, nullptr,
                   g_p1 + 0 + (size_t)f * 64 * 64, 256,
                   bx, by, tid, s1, s2);
    } else {                             // tex0: 6 faces x 8 tiles
        is_t1 = 0;
        int j = b - 768;
        f = j >> 3;
        int q = j & 7;
        int bx = q & 1, by = q >> 1;
        build_tile(t0 + (size_t)f * 128 * 128 * 3, 384,
                   g_p0 + OFF0[1] + (size_t)f * 64 * 64,
                   g_p0 + OFF0[2] + (size_t)f * 32 * 32,
                   g_p0 + OFF0[3] + (size_t)f * 16 * 16, 64,
                   bx, by, tid, s1, s2);
    }

    // last-block-per-face executes the tail (levels 4+ and packed hot set)
    __threadfence();
    __syncthreads();                     // all L3 stores issued + fenced
    if (tid == 0) {
        int cidx = is_t1 ? f : 6 + f;
        unsigned thr = is_t1 ? 128u : 8u;
        unsigned old = atomicAdd(&g_cnt[cidx], 1u);
        if (old == thr - 1u) {
            g_cnt[cidx] = 0;             // reset for next graph replay
            s_exec = 1;
        } else {
            s_exec = 0;
        }
    }
    __syncthreads();
    if (s_exec) {
        __threadfence();                 // acquire: other blocks' L3 via L2
        face_tail(is_t1, f, tid);
    }
}

// ---------------------------------------------------------------------------
// Sampling helpers (R10 form)
// ---------------------------------------------------------------------------
struct TapIdx { int i00, i01, i10, i11; float w00, w01, w10, w11; };

__device__ __forceinline__ TapIdx tap_idx(int R, float u, float v) {
    float x = u * (float)R - 0.5f;
    float y = v * (float)R - 0.5f;
    float x0f = floorf(x), y0f = floorf(y);
    float fx = x - x0f, fy = y - y0f;
    int xi = (int)x0f, yi = (int)y0f;
    int x0 = min(max(xi, 0), R - 1);
    int x1 = min(max(xi + 1, 0), R - 1);
    int y0 = min(max(yi, 0), R - 1);
    int y1 = min(max(yi + 1, 0), R - 1);
    TapIdx t;
    t.i00 = y0 * R + x0; t.i01 = y0 * R + x1;
    t.i10 = y1 * R + x0; t.i11 = y1 * R + x1;
    t.w00 = (1.0f - fx) * (1.0f - fy);
    t.w01 = fx * (1.0f - fy);
    t.w10 = (1.0f - fx) * fy;
    t.w11 = fx * fy;
    return t;
}

// paired-smem bilinear: 2x LDS.128; clamp-before-floor is exactly equivalent.
__device__ __forceinline__ float3 bil_smP(const uint4* __restrict__ b, int R,
                                          float u, float v, float center) {
    float x = fminf(fmaxf(u * (float)R - 0.5f, 0.0f), (float)(R - 1));
    float y = fminf(fmaxf(v * (float)R - 0.5f, 0.0f), (float)(R - 1));
    int x0 = (int)x, y0 = (int)y;
    float fx = x - (float)x0, fy = y - (float)y0;
    int y1 = min(y0 + 1, R - 1);
    uint4 r0 = b[y0 * R + x0];          // (g00, g01)
    uint4 r1 = b[y1 * R + x0];          // (g10, g11)
    float3 g00 = unpack3w(r0.x, r0.y);
    float3 g01 = unpack3w(r0.z, r0.w);
    float3 g10 = unpack3w(r1.x, r1.y);
    float3 g11 = unpack3w(r1.z, r1.w);
    float w00 = (1.0f - fx) * (1.0f - fy);
    float w01 = fx * (1.0f - fy);
    float w10 = (1.0f - fx) * fy;
    float w11 = fx * fy;
    float3 r;
    r.x = w00 * g00.x + w01 * g01.x + w10 * g10.x + w11 * g11.x - center;
    r.y = w00 * g00.y + w01 * g01.y + w10 * g10.y + w11 * g11.y - center;
    r.z = w00 * g00.z + w01 * g01.z + w10 * g10.z + w11 * g11.z - center;
    return r;
}

__device__ __forceinline__ float3 bil4(const float4* __restrict__ t, int R,
                                       int face, float u, float v) {
    TapIdx ti = tap_idx(R, u, v);
    const float4* b = t + (size_t)face * R * R;
    float4 g00 = __ldg(b + ti.i00);
    float4 g01 = __ldg(b + ti.i01);
    float4 g10 = __ldg(b + ti.i10);
    float4 g11 = __ldg(b + ti.i11);
    float3 r;
    r.x = ti.w00 * g00.x + ti.w01 * g01.x + ti.w10 * g10.x + ti.w11 * g11.x;
    r.y = ti.w00 * g00.y + ti.w01 * g01.y + ti.w10 * g10.y + ti.w11 * g11.y;
    r.z = ti.w00 * g00.z + ti.w01 * g01.z + ti.w10 * g10.z + ti.w11 * g11.z;
    return r;
}

__device__ __forceinline__ float3 bil3(const float* __restrict__ t, int R,
                                       int face, float u, float v) {
    TapIdx ti = tap_idx(R, u, v);
    const float* b = t + (size_t)face * R * R * 3;
    const float* p00 = b + (size_t)ti.i00 * 3;
    const float* p01 = b + (size_t)ti.i01 * 3;
    const float* p10 = b + (size_t)ti.i10 * 3;
    const float* p11 = b + (size_t)ti.i11 * 3;
    float3 r;
    r.x = ti.w00 * p00[0] + ti.w01 * p01[0] + ti.w10 * p10[0] + ti.w11 * p11[0];
    r.y = ti.w00 * p00[1] + ti.w01 * p01[1] + ti.w10 * p10[1] + ti.w11 * p11[1];
    r.z = ti.w00 * p00[2] + ti.w01 * p01[2] + ti.w10 * p10[2] + ti.w11 * p11[2];
    return r;
}

// exact mean of a 2x2 base block (same summation order as buildA)
__device__ __noinline__ float3 mean2x2(const float* __restrict__ b,
                                       int sx, int sy) {
    const float* p = b + ((size_t)sy * 512 + sx) * 3;
    const float* q = p + 1536;
    return make_float3(0.25f * (p[0] + p[3] + q[0] + q[3]),
                       0.25f * (p[1] + p[4] + q[1] + q[4]),
                       0.25f * (p[2] + p[5] + q[2] + q[5]));
}

// cold recompute of tex1 level-l (l in {1,2}) texel from the base texture
__device__ __noinline__ float3 tex1_texel_rec(const float* __restrict__ t1,
                                              int face, int l, int x, int y) {
    const float* b = t1 + (size_t)face * 512 * 512 * 3;
    if (l == 1) return mean2x2(b, 2 * x, 2 * y);
    float3 m00 = mean2x2(b, 4 * x, 4 * y);
    float3 m01 = mean2x2(b, 4 * x + 2, 4 * y);
    float3 m10 = mean2x2(b, 4 * x, 4 * y + 2);
    float3 m11 = mean2x2(b, 4 * x + 2, 4 * y + 2);
    return make_float3(0.25f * ((m00.x + m01.x) + (m10.x + m11.x)),
                       0.25f * ((m00.y + m01.y) + (m10.y + m11.y)),
                       0.25f * ((m00.z + m01.z) + (m10.z + m11.z)));
}

__device__ __noinline__ float3 bil_rec1(const float* __restrict__ t1, int l,
                                        int face, float u, float v) {
    int R = 512 >> l;
    float x = u * (float)R - 0.5f;
    float y = v * (float)R - 0.5f;
    float x0f = floorf(x), y0f = floorf(y);
    float fx = x - x0f, fy = y - y0f;
    int xi = (int)x0f, yi = (int)y0f;
    int x0 = min(max(xi, 0), R - 1), x1 = min(max(xi + 1, 0), R - 1);
    int y0 = min(max(yi, 0), R - 1), y1 = min(max(yi + 1, 0), R - 1);
    float3 g00 = tex1_texel_rec(t1, face, l, x0, y0);
    float3 g01 = tex1_texel_rec(t1, face, l, x1, y0);
    float3 g10 = tex1_texel_rec(t1, face, l, x0, y1);
    float3 g11 = tex1_texel_rec(t1, face, l, x1, y1);
    float w00 = (1.0f - fx) * (1.0f - fy), w01 = fx * (1.0f - fy);
    float w10 = (1.0f - fx) * fy,          w11 = fx * fy;
    return make_float3(w00*g00.x + w01*g01.x + w10*g10.x + w11*g11.x,
                       w00*g00.y + w01*g01.y + w10*g10.y + w11*g11.y,
                       w00*g00.z + w01*g01.z + w10*g10.z + w11*g11.z);
}

// per-level fetchers
__device__ __forceinline__ float3 fetch1(const uint4* __restrict__ smp,
                                         const float* __restrict__ t1,
                                         int l, int face, float u, float v) {
    if (l >= 4) {
        int R = 512 >> l;
        return bil_smP(smp + SM1OFF[l] + face * R * R, R, u, v, 1.0f);
    }
    if (l == 3) return bil4(g_p1 + 0, 64, face, u, v);
    if (l == 0) return bil3(t1, 512, face, u, v);
    return bil_rec1(t1, l, face, u, v);          // l in {1,2}: P ~ 3e-9
}

__device__ __forceinline__ float3 fetch0(const uint4* __restrict__ smp,
                                         const float* __restrict__ t0,
                                         int l, int face, float u, float v) {
    if (l >= 3) {
        int R = 128 >> l;
        return bil_smP(smp + SM0OFF[l] + face * R * R, R, u, v, 2.0f);
    }
    if (l == 0) return bil3(t0, 128, face, u, v);
    return bil4(g_p0 + OFF0[l], 128 >> l, face, u, v);
}

// ---------------------------------------------------------------------------
// Persistent sample kernel: paired half4 hot pyramid in 160KB smem, 1 blk/SM.
// ---------------------------------------------------------------------------
__global__ void __launch_bounds__(1024, 1) sample_kernel(
                              const float* __restrict__ vd,
                              const float* __restrict__ sa,
                              const float* __restrict__ nu,
                              const float* __restrict__ t0,
                              const float* __restrict__ t1,
                              const float* __restrict__ pbr,
                              const float* __restrict__ pmul,
                              const float* __restrict__ pmb,
                              float* __restrict__ out, int n) {
    extern __shared__ uint4 smP[];
    int tid = threadIdx.x;

    #pragma unroll
    for (int k = 0; k < 10; k++) {
        int idx = tid + k * 1024;
        smP[idx] = g_hotP[idx];
    }
    __syncthreads();

    float br  = fminf(fmaxf(pbr[0], -1.0f), 2.0f);
    float mul = pmul[0];
    float mb  = pmb[0];

    int stride = gridDim.x * blockDim.x;
    for (int i = blockIdx.x * blockDim.x + tid; i < n; i += stride) {
        float vx = vd[3 * (size_t)i + 0];
        float vy = vd[3 * (size_t)i + 1];
        float vz = vd[3 * (size_t)i + 2];
        float ax = fabsf(vx), ay = fabsf(vy), az = fabsf(vz);
        float ma = fmaxf(ax, fmaxf(ay, az));

        // log(saTexel) = -(log(ma) + 18*ln2);  1/(2 ln 4) = 0.36067376
        float mip = (sa[i] + __logf(ma) + 12.476649250079015f)
                    * 0.36067376022224085f + mb + 0.5f * nu[i];
        mip = fmaxf(mip, 0.0f);

        int face; float sc, tc, den;
        bool is_x = (ax >= ay) && (ax >= az);
        bool is_y = (!is_x) && (ay >= az);
        if (is_x)      { face = (vx >= 0.0f) ? 0 : 1; den = ax; sc = (vx >= 0.0f) ? -vz :  vz; tc = -vy; }
        else if (is_y) { face = (vy >= 0.0f) ? 2 : 3; den = ay; sc =  vx;                      tc = (vy >= 0.0f) ?  vz : -vz; }
        else           { face = (vz >= 0.0f) ? 4 : 5; den = az; sc = (vz >= 0.0f) ?  vx : -vx; tc = -vy; }
        float inv = __fdividef(1.0f, den);
        float u = 0.5f * (sc * inv + 1.0f);
        float v = 0.5f * (tc * inv + 1.0f);

        // tex0 trilinear (lmax=7)
        float m0 = fminf(mip, 7.0f);
        int l0a = (int)m0; float f0 = m0 - (float)l0a;
        float3 s0 = fetch0(smP, t0, l0a, face, u, v);
        if (f0 > 0.0f) {
            float3 c1 = fetch0(smP, t0, l0a + 1, face, u, v);
            float g = 1.0f - f0;
            s0.x = g * s0.x + f0 * c1.x;
            s0.y = g * s0.y + f0 * c1.y;
            s0.z = g * s0.z + f0 * c1.z;
        }
        // tex1 trilinear (lmax=9)
        float m1 = fminf(mip, 9.0f);
        int l1a = (int)m1; float f1 = m1 - (float)l1a;
        float3 s1 = fetch1(smP, t1, l1a, face, u, v);
        if (f1 > 0.0f) {
            float3 c1 = fetch1(smP, t1, l1a + 1, face, u, v);
            float g = 1.0f - f1;
            s1.x = g * s1.x + f1 * c1.x;
            s1.y = g * s1.y + f1 * c1.y;
            s1.z = g * s1.z + f1 * c1.z;
        }

        float ox = fminf(fmaxf(__expf(br + mul * (s0.x + s1.x)), 0.01f), 1000.0f);
        float oy = fminf(fmaxf(__expf(br + mul * (s0.y + s1.y)), 0.01f), 1000.0f);
        float oz = fminf(fmaxf(__expf(br + mul * (s0.z + s1.z)), 0.01f), 1000.0f);
        out[3 * (size_t)i + 0] = ox;
        out[3 * (size_t)i + 1] = oy;
        out[3 * (size_t)i + 2] = oz;
    }
}

extern "C" void kernel_launch(void* const* d_in, const int* in_sizes, int n_in,
                              void* d_out, int out_size) {
    const float* vd  = (const float*)d_in[0];  // viewdirs  [B,3]
    const float* sa  = (const float*)d_in[1];  // saSample  [B]
    const float* nu  = (const float*)d_in[2];  // noise_u   [B]
    const float* t0  = (const float*)d_in[3];  // bg_mat0   [1,6,128,128,3]
    const float* t1  = (const float*)d_in[4];  // bg_mat1   [1,6,512,512,3]
    const float* br  = (const float*)d_in[5];  // brightness scalar
    const float* mul = (const float*)d_in[6];  // mul scalar
    const float* mb  = (const float*)d_in[7];  // mipbias scalar
    int n = in_sizes[1];

    cudaFuncSetAttribute(sample_kernel,
                         cudaFuncAttributeMaxDynamicSharedMemorySize, 163840);

    buildA<<<816, 256>>>(t0, t1);              // L1-3 + fused per-face tails
    sample_kernel<<<148, 1024, 163840>>>(vd, sa, nu, t0, t1, br, mul, mb,
                                         (float*)d_out, n);
}

// round 14
// speedup vs baseline: 1.2884x; 1.2884x over previous
#include <cuda_runtime.h>
#include <cuda_fp16.h>
#include <math.h>

// ---------------------------------------------------------------------------
// Pyramid scratch.
// tex0: float4 levels 1..7 (all kept — tiny).
// tex1: float4 levels 3..9 only (L1/L2 never materialized; cold fallback
//       recomputes exactly from the base texture, P ~ 3e-9).
// g_hotP: PAIRED packed half4 hot set (uint4 per texel = (t[x], t[x+1clamp])):
//         tex1 L4-9 at [0,8190), tex0 L3-7 at [8192,10238)  (uint4 units).
// Hot texels stored CENTERED: tex1 +1.0, tex0 +2.0 (deviations ~0.06 → half
// resolution ~1e-5 absolute).
// ---------------------------------------------------------------------------
__device__ float4 g_p0[32766];
__device__ float4 g_p1[32766];     // tex1 L3..L9, L3 at offset 0
__device__ uint4  g_hotP[10240];   // paired half4 texels, 160KB

__constant__ int OFF0[8]   = {0, 0, 24576, 30720, 32256, 32640, 32736, 32760};
__constant__ int OFF1G[10] = {0, 0, 0, 0, 24576, 30720, 32256, 32640,
                              32736, 32760};                  // tex1, L3=0
// hot texel offsets (uint4 units)
__constant__ int SM1OFF[10] = {0, 0, 0, 0, 0, 6144, 7680, 8064, 8160, 8184};
__constant__ int SM0OFF[8]  = {0, 0, 0, 8192, 9728, 10112, 10208, 10232};

__device__ __forceinline__ uint2 pack3(float x, float y, float z) {
    __half2 a = __floats2half2_rn(x, y);
    __half2 b = __floats2half2_rn(z, 0.0f);
    uint2 r;
    r.x = *reinterpret_cast<unsigned*>(&a);
    r.y = *reinterpret_cast<unsigned*>(&b);
    return r;
}

__device__ __forceinline__ __half2 u2h(unsigned w) {
    return *reinterpret_cast<__half2*>(&w);
}

// ---------------------------------------------------------------------------
// buildA: L1..L3 of both pyramids (R10 form). 256 threads, 32x16 L1 tiles.
// tex1: L1/L2 live only in smem; only L3 is stored to global.
// ---------------------------------------------------------------------------
__device__ __forceinline__ void build_tile(
    const float* __restrict__ in, int inRowF,
    float4* __restrict__ L1g,      // may be null (tex1)
    float4* __restrict__ L2g,      // may be null (tex1)
    float4* __restrict__ L3g, int R1,
    int bx, int by, int tid,
    float4* s1, float4* s2)
{
    int lx2 = (tid & 15) * 2;
    int ly  = tid >> 4;
    int X0 = bx * 32 + lx2;
    int Y  = by * 16 + ly;

    const float* r0 = in + (size_t)(2 * Y) * inRowF + 6 * X0;
    const float* r1 = r0 + inRowF;
    float a[12], b[12];
    #pragma unroll
    for (int q = 0; q < 3; q++) {
        *(float4*)(a + 4 * q) = __ldg((const float4*)r0 + q);
        *(float4*)(b + 4 * q) = __ldg((const float4*)r1 + q);
    }
    #pragma unroll
    for (int k = 0; k < 2; k++) {
        float cx = 0.25f * (a[6*k+0] + a[6*k+3] + b[6*k+0] + b[6*k+3]);
        float cy = 0.25f * (a[6*k+1] + a[6*k+4] + b[6*k+1] + b[6*k+4]);
        float cz = 0.25f * (a[6*k+2] + a[6*k+5] + b[6*k+2] + b[6*k+5]);
        float4 t = make_float4(cx, cy, cz, 0.0f);
        s1[ly * 32 + lx2 + k] = t;
        if (L1g) L1g[(size_t)Y * R1 + X0 + k] = t;
    }
    __syncthreads();

    if (tid < 128) {
        int x2 = tid & 15, y2 = tid >> 4;
        float4 p00 = s1[(2*y2) * 32 + 2*x2];
        float4 p01 = s1[(2*y2) * 32 + 2*x2 + 1];
        float4 p10 = s1[(2*y2+1) * 32 + 2*x2];
        float4 p11 = s1[(2*y2+1) * 32 + 2*x2 + 1];
        float4 m = make_float4(0.25f * (p00.x + p01.x + p10.x + p11.x),
                               0.25f * (p00.y + p01.y + p10.y + p11.y),
                               0.25f * (p00.z + p01.z + p10.z + p11.z), 0.0f);
        s2[y2 * 16 + x2] = m;
        if (L2g) {
            int R2 = R1 >> 1;
            L2g[(size_t)(by * 8 + y2) * R2 + bx * 16 + x2] = m;
        }
    }
    __syncthreads();

    if (tid < 32) {
        int x3 = tid & 7, y3 = tid >> 3;
        float4 p00 = s2[(2*y3) * 16 + 2*x3];
        float4 p01 = s2[(2*y3) * 16 + 2*x3 + 1];
        float4 p10 = s2[(2*y3+1) * 16 + 2*x3];
        float4 p11 = s2[(2*y3+1) * 16 + 2*x3 + 1];
        float4 m = make_float4(0.25f * (p00.x + p01.x + p10.x + p11.x),
                               0.25f * (p00.y + p01.y + p10.y + p11.y),
                               0.25f * (p00.z + p01.z + p10.z + p11.z), 0.0f);
        int R3 = R1 >> 2;
        L3g[(size_t)(by * 4 + y3) * R3 + bx * 8 + x3] = m;
    }
}

__global__ void __launch_bounds__(256) buildA(const float* __restrict__ t0,
                                              const float* __restrict__ t1) {
    __shared__ float4 s1[32 * 16];
    __shared__ float4 s2[16 * 8];
    int b = blockIdx.x, tid = threadIdx.x;
    if (b < 768) {                       // tex1: 6 faces x 128 tiles
        int f = b >> 7, q = b & 127;
        int bx = q & 7, by = q >> 3;
        build_tile(t1 + (size_t)f * 512 * 512 * 3, 1536,
                   nullptr, nullptr,
                   g_p1 + 0 + (size_t)f * 64 * 64, 256,
                   bx, by, tid, s1, s2);
    } else {                             // tex0: 6 faces x 8 tiles
        int j = b - 768;
        int f = j >> 3, q = j & 7;
        int bx = q & 1, by = q >> 1;
        build_tile(t0 + (size_t)f * 128 * 128 * 3, 384,
                   g_p0 + OFF0[1] + (size_t)f * 64 * 64,
                   g_p0 + OFF0[2] + (size_t)f * 32 * 32,
                   g_p0 + OFF0[3] + (size_t)f * 16 * 16, 64,
                   bx, by, tid, s1, s2);
    }
}

// ---------------------------------------------------------------------------
// buildTail: reduce L4+ per face; write float4 cold copies + PAIRED hot set.
// ---------------------------------------------------------------------------
__device__ __forceinline__ void write_pairs(const float4* __restrict__ src,
                                            uint4* __restrict__ dst,
                                            int R, float center, int tid,
                                            int nthreads) {
    for (int i = tid; i < R * R; i += nthreads) {
        int x = i % R;
        float4 v0 = src[i];
        float4 v1 = src[(x < R - 1) ? i + 1 : i];
        uint2 p0 = pack3(v0.x + center, v0.y + center, v0.z + center);
        uint2 p1 = pack3(v1.x + center, v1.y + center, v1.z + center);
        dst[i] = make_uint4(p0.x, p0.y, p1.x, p1.y);
    }
}

__global__ void buildTail() {
    extern __shared__ float4 sm[];
    float4* A = sm;
    float4* Bb = sm + 4096;

    int b = blockIdx.x;
    float4* pyr; const int* goff; const int* soff;
    int Rsrc, lmax, f; float center;
    if (b < 6) { f = b;     pyr = g_p1; goff = OFF1G; soff = SM1OFF;
                 Rsrc = 64; lmax = 9; center = 1.0f; }
    else       { f = b - 6; pyr = g_p0; goff = OFF0;  soff = SM0OFF;
                 Rsrc = 16; lmax = 7; center = 2.0f; }

    const float4* src = pyr + goff[3] + (size_t)f * Rsrc * Rsrc;
    for (int i = threadIdx.x; i < Rsrc * Rsrc; i += blockDim.x) A[i] = src[i];
    __syncthreads();

    if (b >= 6)   // tex0 L3 belongs to the hot set
        write_pairs(A, g_hotP + soff[3] + f * Rsrc * Rsrc, Rsrc, center,
                    threadIdx.x, blockDim.x);

    int curR = Rsrc;
    for (int l = 4; l <= lmax; l++) {
        int R = curR >> 1;
        float4* dst_g = pyr + goff[l] + (size_t)f * R * R;
        for (int i = threadIdx.x; i < R * R; i += blockDim.x) {
            int x = i % R, y = i / R;
            const float4* p = A + (size_t)(2 * y) * curR + 2 * x;
            const float4* q = p + curR;
            float4 m = make_float4(
                0.25f * (p[0].x + p[1].x + q[0].x + q[1].x),
                0.25f * (p[0].y + p[1].y + q[0].y + q[1].y),
                0.25f * (p[0].z + p[1].z + q[0].z + q[1].z), 0.0f);
            Bb[i] = m;
            dst_g[i] = m;
        }
        __syncthreads();
        write_pairs(Bb, g_hotP + soff[l] + f * R * R, R, center,
                    threadIdx.x, blockDim.x);
        float4* tmp = A; A = Bb; Bb = tmp;
        curR = R;
    }
}

// ---------------------------------------------------------------------------
// Sampling helpers
// ---------------------------------------------------------------------------
struct TapIdx { int i00, i01, i10, i11; float w00, w01, w10, w11; };

__device__ __forceinline__ TapIdx tap_idx(int R, float u, float v) {
    float x = u * (float)R - 0.5f;
    float y = v * (float)R - 0.5f;
    float x0f = floorf(x), y0f = floorf(y);
    float fx = x - x0f, fy = y - y0f;
    int xi = (int)x0f, yi = (int)y0f;
    int x0 = min(max(xi, 0), R - 1);
    int x1 = min(max(xi + 1, 0), R - 1);
    int y0 = min(max(yi, 0), R - 1);
    int y1 = min(max(yi + 1, 0), R - 1);
    TapIdx t;
    t.i00 = y0 * R + x0; t.i01 = y0 * R + x1;
    t.i10 = y1 * R + x0; t.i11 = y1 * R + x1;
    t.w00 = (1.0f - fx) * (1.0f - fy);
    t.w01 = fx * (1.0f - fy);
    t.w10 = (1.0f - fx) * fy;
    t.w11 = fx * fy;
    return t;
}

// paired-smem bilinear in HALF2 arithmetic: 2x LDS.128, lerps in HFMA2.
// Texels are small centered deviations, so half math error ~1e-5 absolute.
// Clamp-before-floor is exactly equivalent to reference clamp-after-floor.
__device__ __forceinline__ float3 bil_smP(const uint4* __restrict__ b, int R,
                                          float u, float v, float center) {
    float x = fminf(fmaxf(u * (float)R - 0.5f, 0.0f), (float)(R - 1));
    float y = fminf(fmaxf(v * (float)R - 0.5f, 0.0f), (float)(R - 1));
    int x0 = (int)x, y0 = (int)y;
    float fx = x - (float)x0, fy = y - (float)y0;
    int y1 = min(y0 + 1, R - 1);
    uint4 r0 = b[y0 * R + x0];          // (g00.xy, g00.z_, g01.xy, g01.z_)
    uint4 r1 = b[y1 * R + x0];          // (g10.xy, g10.z_, g11.xy, g11.z_)
    __half2 fx2 = __float2half2_rn(fx);
    __half2 fy2 = __float2half2_rn(fy);
    __half2 topxy = __hfma2(fx2, __hsub2(u2h(r0.z), u2h(r0.x)), u2h(r0.x));
    __half2 topz  = __hfma2(fx2, __hsub2(u2h(r0.w), u2h(r0.y)), u2h(r0.y));
    __half2 botxy = __hfma2(fx2, __hsub2(u2h(r1.z), u2h(r1.x)), u2h(r1.x));
    __half2 botz  = __hfma2(fx2, __hsub2(u2h(r1.w), u2h(r1.y)), u2h(r1.y));
    __half2 rxy = __hfma2(fy2, __hsub2(botxy, topxy), topxy);
    __half2 rz  = __hfma2(fy2, __hsub2(botz,  topz),  topz);
    float2 xyf = __half22float2(rxy);
    return make_float3(xyf.x - center, xyf.y - center,
                       __low2float(rz) - center);
}

__device__ __forceinline__ float3 bil4(const float4* __restrict__ t, int R,
                                       int face, float u, float v) {
    TapIdx ti = tap_idx(R, u, v);
    const float4* b = t + (size_t)face * R * R;
    float4 g00 = __ldg(b + ti.i00);
    float4 g01 = __ldg(b + ti.i01);
    float4 g10 = __ldg(b + ti.i10);
    float4 g11 = __ldg(b + ti.i11);
    float3 r;
    r.x = ti.w00 * g00.x + ti.w01 * g01.x + ti.w10 * g10.x + ti.w11 * g11.x;
    r.y = ti.w00 * g00.y + ti.w01 * g01.y + ti.w10 * g10.y + ti.w11 * g11.y;
    r.z = ti.w00 * g00.z + ti.w01 * g01.z + ti.w10 * g10.z + ti.w11 * g11.z;
    return r;
}

__device__ __forceinline__ float3 bil3(const float* __restrict__ t, int R,
                                       int face, float u, float v) {
    TapIdx ti = tap_idx(R, u, v);
    const float* b = t + (size_t)face * R * R * 3;
    const float* p00 = b + (size_t)ti.i00 * 3;
    const float* p01 = b + (size_t)ti.i01 * 3;
    const float* p10 = b + (size_t)ti.i10 * 3;
    const float* p11 = b + (size_t)ti.i11 * 3;
    float3 r;
    r.x = ti.w00 * p00[0] + ti.w01 * p01[0] + ti.w10 * p10[0] + ti.w11 * p11[0];
    r.y = ti.w00 * p00[1] + ti.w01 * p01[1] + ti.w10 * p10[1] + ti.w11 * p11[1];
    r.z = ti.w00 * p00[2] + ti.w01 * p01[2] + ti.w10 * p10[2] + ti.w11 * p11[2];
    return r;
}

// exact mean of a 2x2 base block (same summation order as buildA)
__device__ __noinline__ float3 mean2x2(const float* __restrict__ b,
                                       int sx, int sy) {
    const float* p = b + ((size_t)sy * 512 + sx) * 3;
    const float* q = p + 1536;
    return make_float3(0.25f * (p[0] + p[3] + q[0] + q[3]),
                       0.25f * (p[1] + p[4] + q[1] + q[4]),
                       0.25f * (p[2] + p[5] + q[2] + q[5]));
}

// cold recompute of tex1 level-l (l in {1,2}) texel from the base texture
__device__ __noinline__ float3 tex1_texel_rec(const float* __restrict__ t1,
                                              int face, int l, int x, int y) {
    const float* b = t1 + (size_t)face * 512 * 512 * 3;
    if (l == 1) return mean2x2(b, 2 * x, 2 * y);
    float3 m00 = mean2x2(b, 4 * x, 4 * y);
    float3 m01 = mean2x2(b, 4 * x + 2, 4 * y);
    float3 m10 = mean2x2(b, 4 * x, 4 * y + 2);
    float3 m11 = mean2x2(b, 4 * x + 2, 4 * y + 2);
    return make_float3(0.25f * ((m00.x + m01.x) + (m10.x + m11.x)),
                       0.25f * ((m00.y + m01.y) + (m10.y + m11.y)),
                       0.25f * ((m00.z + m01.z) + (m10.z + m11.z)));
}

__device__ __noinline__ float3 bil_rec1(const float* __restrict__ t1, int l,
                                        int face, float u, float v) {
    int R = 512 >> l;
    float x = u * (float)R - 0.5f;
    float y = v * (float)R - 0.5f;
    float x0f = floorf(x), y0f = floorf(y);
    float fx = x - x0f, fy = y - y0f;
    int xi = (int)x0f, yi = (int)y0f;
    int x0 = min(max(xi, 0), R - 1), x1 = min(max(xi + 1, 0), R - 1);
    int y0 = min(max(yi, 0), R - 1), y1 = min(max(yi + 1, 0), R - 1);
    float3 g00 = tex1_texel_rec(t1, face, l, x0, y0);
    float3 g01 = tex1_texel_rec(t1, face, l, x1, y0);
    float3 g10 = tex1_texel_rec(t1, face, l, x0, y1);
    float3 g11 = tex1_texel_rec(t1, face, l, x1, y1);
    float w00 = (1.0f - fx) * (1.0f - fy), w01 = fx * (1.0f - fy);
    float w10 = (1.0f - fx) * fy,          w11 = fx * fy;
    return make_float3(w00*g00.x + w01*g01.x + w10*g10.x + w11*g11.x,
                       w00*g00.y + w01*g01.y + w10*g10.y + w11*g11.y,
                       w00*g00.z + w01*g01.z + w10*g10.z + w11*g11.z);
}

// per-level fetchers
__device__ __forceinline__ float3 fetch1(const uint4* __restrict__ smp,
                                         const float* __restrict__ t1,
                                         int l, int face, float u, float v) {
    if (l >= 4) {
        int R = 512 >> l;
        return bil_smP(smp + SM1OFF[l] + face * R * R, R, u, v, 1.0f);
    }
    if (l == 3) return bil4(g_p1 + 0, 64, face, u, v);
    if (l == 0) return bil3(t1, 512, face, u, v);
    return bil_rec1(t1, l, face, u, v);          // l in {1,2}: P ~ 3e-9
}

__device__ __forceinline__ float3 fetch0(const uint4* __restrict__ smp,
                                         const float* __restrict__ t0,
                                         int l, int face, float u, float v) {
    if (l >= 3) {
        int R = 128 >> l;
        return bil_smP(smp + SM0OFF[l] + face * R * R, R, u, v, 2.0f);
    }
    if (l == 0) return bil3(t0, 128, face, u, v);
    return bil4(g_p0 + OFF0[l], 128 >> l, face, u, v);
}

// ---------------------------------------------------------------------------
// Persistent sample kernel: paired half4 hot pyramid in 160KB smem, 1 blk/SM.
// ---------------------------------------------------------------------------
__global__ void __launch_bounds__(1024, 1) sample_kernel(
                              const float* __restrict__ vd,
                              const float* __restrict__ sa,
                              const float* __restrict__ nu,
                              const float* __restrict__ t0,
                              const float* __restrict__ t1,
                              const float* __restrict__ pbr,
                              const float* __restrict__ pmul,
                              const float* __restrict__ pmb,
                              float* __restrict__ out, int n) {
    extern __shared__ uint4 smP[];
    int tid = threadIdx.x;

    #pragma unroll
    for (int k = 0; k < 10; k++) {
        int idx = tid + k * 1024;
        smP[idx] = g_hotP[idx];
    }
    __syncthreads();

    float br  = fminf(fmaxf(pbr[0], -1.0f), 2.0f);
    float mul = pmul[0];
    float mb  = pmb[0];

    int stride = gridDim.x * blockDim.x;
    for (int i = blockIdx.x * blockDim.x + tid; i < n; i += stride) {
        float vx = vd[3 * (size_t)i + 0];
        float vy = vd[3 * (size_t)i + 1];
        float vz = vd[3 * (size_t)i + 2];
        float ax = fabsf(vx), ay = fabsf(vy), az = fabsf(vz);
        float ma = fmaxf(ax, fmaxf(ay, az));

        // log(saTexel) = -(log(ma) + 18*ln2);  1/(2 ln 4) = 0.36067376
        float mip = (sa[i] + __logf(ma) + 12.476649250079015f)
                    * 0.36067376022224085f + mb + 0.5f * nu[i];
        mip = fmaxf(mip, 0.0f);

        int face; float sc, tc, den;
        bool is_x = (ax >= ay) && (ax >= az);
        bool is_y = (!is_x) && (ay >= az);
        if (is_x)      { face = (vx >= 0.0f) ? 0 : 1; den = ax; sc = (vx >= 0.0f) ? -vz :  vz; tc = -vy; }
        else if (is_y) { face = (vy >= 0.0f) ? 2 : 3; den = ay; sc =  vx;                      tc = (vy >= 0.0f) ?  vz : -vz; }
        else           { face = (vz >= 0.0f) ? 4 : 5; den = az; sc = (vz >= 0.0f) ?  vx : -vx; tc = -vy; }
        float inv = __fdividef(1.0f, den);
        float u = 0.5f * (sc * inv + 1.0f);
        float v = 0.5f * (tc * inv + 1.0f);

        // tex0 trilinear (lmax=7)
        float m0 = fminf(mip, 7.0f);
        int l0a = (int)m0; float f0 = m0 - (float)l0a;
        float3 s0 = fetch0(smP, t0, l0a, face, u, v);
        if (f0 > 0.0f) {
            float3 c1 = fetch0(smP, t0, l0a + 1, face, u, v);
            s0.x += f0 * (c1.x - s0.x);
            s0.y += f0 * (c1.y - s0.y);
            s0.z += f0 * (c1.z - s0.z);
        }
        // tex1 trilinear (lmax=9)
        float m1 = fminf(mip, 9.0f);
        int l1a = (int)m1; float f1 = m1 - (float)l1a;
        float3 s1 = fetch1(smP, t1, l1a, face, u, v);
        if (f1 > 0.0f) {
            float3 c1 = fetch1(smP, t1, l1a + 1, face, u, v);
            s1.x += f1 * (c1.x - s1.x);
            s1.y += f1 * (c1.y - s1.y);
            s1.z += f1 * (c1.z - s1.z);
        }

        float ox = fminf(fmaxf(__expf(br + mul * (s0.x + s1.x)), 0.01f), 1000.0f);
        float oy = fminf(fmaxf(__expf(br + mul * (s0.y + s1.y)), 0.01f), 1000.0f);
        float oz = fminf(fmaxf(__expf(br + mul * (s0.z + s1.z)), 0.01f), 1000.0f);
        out[3 * (size_t)i + 0] = ox;
        out[3 * (size_t)i + 1] = oy;
        out[3 * (size_t)i + 2] = oz;
    }
}

extern "C" void kernel_launch(void* const* d_in, const int* in_sizes, int n_in,
                              void* d_out, int out_size) {
    const float* vd  = (const float*)d_in[0];  // viewdirs  [B,3]
    const float* sa  = (const float*)d_in[1];  // saSample  [B]
    const float* nu  = (const float*)d_in[2];  // noise_u   [B]
    const float* t0  = (const float*)d_in[3];  // bg_mat0   [1,6,128,128,3]
    const float* t1  = (const float*)d_in[4];  // bg_mat1   [1,6,512,512,3]
    const float* br  = (const float*)d_in[5];  // brightness scalar
    const float* mul = (const float*)d_in[6];  // mul scalar
    const float* mb  = (const float*)d_in[7];  // mipbias scalar
    int n = in_sizes[1];

    cudaFuncSetAttribute(buildTail, cudaFuncAttributeMaxDynamicSharedMemorySize,
                         81920);
    cudaFuncSetAttribute(sample_kernel,
                         cudaFuncAttributeMaxDynamicSharedMemorySize, 163840);

    buildA<<<816, 256>>>(t0, t1);              // L1-3 (tex1 L1/L2 smem-only)
    buildTail<<<12, 256, 81920>>>();           // L4+ float4 + paired hot set
    sample_kernel<<<148, 1024, 163840>>>(vd, sa, nu, t0, t1, br, mul, mb,
                                         (float*)d_out, n);
}